// round 1
// baseline (speedup 1.0000x reference)
#include <cuda_runtime.h>
#include <cstdint>

#define BATCH 4
#define S_LEN 2048
#define EMB   1024
#define NH    16
#define DH    64

// Scratch (allocation-free rule: __device__ globals)
__device__ float g_Q[BATCH * NH * S_LEN * DH];   // [B,H,S,Dh]
__device__ float g_K[BATCH * NH * S_LEN * DH];
__device__ float g_V[BATCH * NH * S_LEN * DH];
__device__ float g_Y[BATCH * S_LEN * EMB];       // merged heads [B,S,E]

// ---------------------------------------------------------------------------
// Tiled GEMM: y = X @ W^T.  BM=BN=64, BK=16, 256 threads, 4x4 per thread.
// qkv variant: blockIdx.z selects W/dst, stores into [B,H,S,Dh] layout.
// ---------------------------------------------------------------------------
__global__ __launch_bounds__(256) void gemm_qkv_kernel(
    const float* __restrict__ X,
    const float* __restrict__ Wq,
    const float* __restrict__ Wk,
    const float* __restrict__ Wv)
{
    const float* W   = (blockIdx.z == 0) ? Wq : (blockIdx.z == 1) ? Wk : Wv;
    float*       dst = (blockIdx.z == 0) ? g_Q : (blockIdx.z == 1) ? g_K : g_V;

    __shared__ float As[16][65];   // [k][m]
    __shared__ float Bs[16][65];   // [k][n]

    const int tid = threadIdx.x;
    const int tx = tid & 15, ty = tid >> 4;
    const int m0 = blockIdx.x * 64, n0 = blockIdx.y * 64;
    const int lr = tid >> 2;            // 0..63
    const int lk = (tid & 3) * 4;       // 0,4,8,12

    float acc[4][4] = {};

    for (int k0 = 0; k0 < EMB; k0 += 16) {
        float4 a = *(const float4*)&X[(size_t)(m0 + lr) * EMB + k0 + lk];
        float4 b = *(const float4*)&W[(size_t)(n0 + lr) * EMB + k0 + lk];
        __syncthreads();
        As[lk + 0][lr] = a.x; As[lk + 1][lr] = a.y;
        As[lk + 2][lr] = a.z; As[lk + 3][lr] = a.w;
        Bs[lk + 0][lr] = b.x; Bs[lk + 1][lr] = b.y;
        Bs[lk + 2][lr] = b.z; Bs[lk + 3][lr] = b.w;
        __syncthreads();
#pragma unroll
        for (int kk = 0; kk < 16; kk++) {
            float av[4], bv[4];
#pragma unroll
            for (int i = 0; i < 4; i++) av[i] = As[kk][ty * 4 + i];
#pragma unroll
            for (int j = 0; j < 4; j++) bv[j] = Bs[kk][tx * 4 + j];
#pragma unroll
            for (int i = 0; i < 4; i++)
#pragma unroll
                for (int j = 0; j < 4; j++)
                    acc[i][j] = fmaf(av[i], bv[j], acc[i][j]);
        }
    }

#pragma unroll
    for (int i = 0; i < 4; i++) {
        const int m = m0 + ty * 4 + i;
        const int b = m >> 11;          // /2048
        const int s = m & 2047;
#pragma unroll
        for (int j = 0; j < 4; j++) {
            const int n = n0 + tx * 4 + j;
            const int h = n >> 6;       // /64
            const int d = n & 63;
            dst[((((size_t)b * NH + h) * S_LEN + s) << 6) + d] = acc[i][j];
        }
    }
}

// Output projection: out = Y @ Wo^T, standard row-major output.
__global__ __launch_bounds__(256) void gemm_out_kernel(
    const float* __restrict__ Wo, float* __restrict__ out)
{
    __shared__ float As[16][65];
    __shared__ float Bs[16][65];

    const int tid = threadIdx.x;
    const int tx = tid & 15, ty = tid >> 4;
    const int m0 = blockIdx.x * 64, n0 = blockIdx.y * 64;
    const int lr = tid >> 2;
    const int lk = (tid & 3) * 4;

    float acc[4][4] = {};

    for (int k0 = 0; k0 < EMB; k0 += 16) {
        float4 a = *(const float4*)&g_Y[(size_t)(m0 + lr) * EMB + k0 + lk];
        float4 b = *(const float4*)&Wo[(size_t)(n0 + lr) * EMB + k0 + lk];
        __syncthreads();
        As[lk + 0][lr] = a.x; As[lk + 1][lr] = a.y;
        As[lk + 2][lr] = a.z; As[lk + 3][lr] = a.w;
        Bs[lk + 0][lr] = b.x; Bs[lk + 1][lr] = b.y;
        Bs[lk + 2][lr] = b.z; Bs[lk + 3][lr] = b.w;
        __syncthreads();
#pragma unroll
        for (int kk = 0; kk < 16; kk++) {
            float av[4], bv[4];
#pragma unroll
            for (int i = 0; i < 4; i++) av[i] = As[kk][ty * 4 + i];
#pragma unroll
            for (int j = 0; j < 4; j++) bv[j] = Bs[kk][tx * 4 + j];
#pragma unroll
            for (int i = 0; i < 4; i++)
#pragma unroll
                for (int j = 0; j < 4; j++)
                    acc[i][j] = fmaf(av[i], bv[j], acc[i][j]);
        }
    }

#pragma unroll
    for (int i = 0; i < 4; i++)
#pragma unroll
        for (int j = 0; j < 4; j++)
            out[(size_t)(m0 + ty * 4 + i) * EMB + n0 + tx * 4 + j] = acc[i][j];
}

// ---------------------------------------------------------------------------
// Flash attention, causal. 64 query rows per block, 64-key tiles, Dh=64.
// 256 threads; thread (tx,ty) owns rows ty*4..+3 and cols/dh tx*4..+3.
// Online softmax state is register-replicated across the 16 lanes of a row
// (all compute identical values via butterfly shuffles).
// ---------------------------------------------------------------------------
#define FLASH_SMEM ((4096 + 64 * 65 + 4096 + 4096) * 4)   // Qs,Ks(pad),Vs,Ps

__global__ __launch_bounds__(256) void flash_kernel()
{
    const int qi = blockIdx.x;      // query tile 0..31
    const int bh = blockIdx.y;      // 0..63

    extern __shared__ float sm[];
    float* Qs = sm;                 // [64][64]  (broadcast reads: no pad needed)
    float* Ks = Qs + 4096;          // [64][65]  (strided reads: pad)
    float* Vs = Ks + 64 * 65;       // [64][64]
    float* Ps = Vs + 4096;          // [64][64]

    const float* Qg  = g_Q + ((size_t)bh * S_LEN + (size_t)qi * 64) * DH;
    const float* Kg0 = g_K + (size_t)bh * S_LEN * DH;
    const float* Vg0 = g_V + (size_t)bh * S_LEN * DH;

    const int tid = threadIdx.x;
    const int tx = tid & 15, ty = tid >> 4;
    const int lr = tid >> 2;            // 0..63
    const int lc = (tid & 3) * 4;       // 0,4,8,12

    // Load Q tile, folding in softmax scale 1/sqrt(64)
#pragma unroll
    for (int q = 0; q < 4; q++) {
        float4 v = *(const float4*)&Qg[lr * DH + lc + 16 * q];
        float* p = &Qs[lr * 64 + lc + 16 * q];
        p[0] = v.x * 0.125f; p[1] = v.y * 0.125f;
        p[2] = v.z * 0.125f; p[3] = v.w * 0.125f;
    }

    float mprev[4], lsum[4], acc[4][4];
#pragma unroll
    for (int i = 0; i < 4; i++) {
        mprev[i] = -1e30f; lsum[i] = 0.f;
#pragma unroll
        for (int j = 0; j < 4; j++) acc[i][j] = 0.f;
    }

    for (int kj = 0; kj <= qi; kj++) {
        __syncthreads();    // Qs visible (iter 0) / previous PV done
        const float* Kg = Kg0 + (size_t)kj * 64 * DH;
        const float* Vg = Vg0 + (size_t)kj * 64 * DH;
#pragma unroll
        for (int q = 0; q < 4; q++) {
            float4 kv = *(const float4*)&Kg[lr * DH + lc + 16 * q];
            float* kp = &Ks[lr * 65 + lc + 16 * q];
            kp[0] = kv.x; kp[1] = kv.y; kp[2] = kv.z; kp[3] = kv.w;
            float4 vv = *(const float4*)&Vg[lr * DH + lc + 16 * q];
            float* vp = &Vs[lr * 64 + lc + 16 * q];
            vp[0] = vv.x; vp[1] = vv.y; vp[2] = vv.z; vp[3] = vv.w;
        }
        __syncthreads();

        // S = Q K^T (4x4 per thread)
        float s[4][4] = {};
#pragma unroll 8
        for (int d = 0; d < 64; d++) {
            float qv[4], kv[4];
#pragma unroll
            for (int i = 0; i < 4; i++) qv[i] = Qs[(ty * 4 + i) * 64 + d];
#pragma unroll
            for (int j = 0; j < 4; j++) kv[j] = Ks[(tx * 4 + j) * 65 + d];
#pragma unroll
            for (int i = 0; i < 4; i++)
#pragma unroll
                for (int j = 0; j < 4; j++)
                    s[i][j] = fmaf(qv[i], kv[j], s[i][j]);
        }

        // Causal mask (only diagonal tile needs it)
        if (kj == qi) {
#pragma unroll
            for (int i = 0; i < 4; i++)
#pragma unroll
                for (int j = 0; j < 4; j++)
                    if (tx * 4 + j > ty * 4 + i) s[i][j] = -1e30f;
        }

        // Online softmax update, row stats replicated across the 16 row lanes
#pragma unroll
        for (int i = 0; i < 4; i++) {
            float tm = s[i][0];
#pragma unroll
            for (int j = 1; j < 4; j++) tm = fmaxf(tm, s[i][j]);
#pragma unroll
            for (int o = 1; o < 16; o <<= 1)
                tm = fmaxf(tm, __shfl_xor_sync(0xffffffffu, tm, o));
            const float mnew  = fmaxf(mprev[i], tm);
            const float alpha = __expf(mprev[i] - mnew);
            float psum = 0.f;
#pragma unroll
            for (int j = 0; j < 4; j++) {
                const float p = __expf(s[i][j] - mnew);
                Ps[(ty * 4 + i) * 64 + tx * 4 + j] = p;
                psum += p;
            }
#pragma unroll
            for (int o = 1; o < 16; o <<= 1)
                psum += __shfl_xor_sync(0xffffffffu, psum, o);
            lsum[i]  = lsum[i] * alpha + psum;
            mprev[i] = mnew;
#pragma unroll
            for (int d = 0; d < 4; d++) acc[i][d] *= alpha;
        }
        __syncthreads();    // Ps visible

        // O += P @ V
#pragma unroll 8
        for (int j = 0; j < 64; j++) {
            float pv[4], vv[4];
#pragma unroll
            for (int i = 0; i < 4; i++) pv[i] = Ps[(ty * 4 + i) * 64 + j];
#pragma unroll
            for (int d = 0; d < 4; d++) vv[d] = Vs[j * 64 + tx * 4 + d];
#pragma unroll
            for (int i = 0; i < 4; i++)
#pragma unroll
                for (int d = 0; d < 4; d++)
                    acc[i][d] = fmaf(pv[i], vv[d], acc[i][d]);
        }
    }

    // Epilogue: normalize, write merged-head [B,S,E]
    const int b = bh >> 4, h = bh & 15;
#pragma unroll
    for (int i = 0; i < 4; i++) {
        const int sq = qi * 64 + ty * 4 + i;
        const float inv = 1.0f / lsum[i];
#pragma unroll
        for (int d = 0; d < 4; d++)
            g_Y[((size_t)(b * S_LEN + sq)) * EMB + h * DH + tx * 4 + d] =
                acc[i][d] * inv;
    }
}

// ---------------------------------------------------------------------------
extern "C" void kernel_launch(void* const* d_in, const int* in_sizes, int n_in,
                              void* d_out, int out_size)
{
    (void)in_sizes; (void)n_in; (void)out_size;
    const float* x  = (const float*)d_in[0];
    const float* Wq = (const float*)d_in[1];
    const float* Wk = (const float*)d_in[2];
    const float* Wv = (const float*)d_in[3];
    const float* Wo = (const float*)d_in[4];
    float* out = (float*)d_out;

    static bool attr_done = false;  // idempotent attribute set (not a work guard)
    if (!attr_done) {
        cudaFuncSetAttribute(flash_kernel,
                             cudaFuncAttributeMaxDynamicSharedMemorySize,
                             FLASH_SMEM);
        attr_done = true;
    }

    // 1) QKV projections: M=8192, N=1024 per weight
    gemm_qkv_kernel<<<dim3(128, 16, 3), 256>>>(x, Wq, Wk, Wv);
    // 2) Causal flash attention per (query-tile, b*h)
    flash_kernel<<<dim3(32, BATCH * NH), 256, FLASH_SMEM>>>();
    // 3) Output projection
    gemm_out_kernel<<<dim3(128, 16), 256>>>(Wo, out);
}

// round 4
// speedup vs baseline: 1.5430x; 1.5430x over previous
#include <cuda_runtime.h>
#include <cstdint>

#define BATCH 4
#define S_LEN 2048
#define EMB   1024
#define NH    16
#define DH    64

// Scratch (allocation-free rule: __device__ globals)
__device__ float g_Q[BATCH * NH * S_LEN * DH];   // [B,H,S,Dh]
__device__ float g_K[BATCH * NH * S_LEN * DH];
__device__ float g_V[BATCH * NH * S_LEN * DH];
__device__ float g_Y[BATCH * S_LEN * EMB];       // merged heads [B,S,E]

// ===========================================================================
// Helpers
// ===========================================================================
__device__ __forceinline__ uint32_t smem_u32(const void* p) {
    uint32_t a;
    asm("{ .reg .u64 t; cvta.to.shared.u64 t, %1; cvt.u32.u64 %0, t; }"
        : "=r"(a) : "l"(p));
    return a;
}
__device__ __forceinline__ void cp_async16(uint32_t s, const void* g) {
    asm volatile("cp.async.cg.shared.global [%0], [%1], 16;" :: "r"(s), "l"(g));
}
__device__ __forceinline__ void cp_commit() {
    asm volatile("cp.async.commit_group;" ::: "memory");
}
template <int N>
__device__ __forceinline__ void cp_wait_group() {
    asm volatile("cp.async.wait_group %0;" :: "n"(N) : "memory");
}
// mma.sync m16n8k8 TF32 (legacy tensor path — compiles for base sm_103)
__device__ __forceinline__ void mma_tf32(float* c, const uint32_t* a, const uint32_t* b) {
    asm volatile(
        "mma.sync.aligned.m16n8k8.row.col.f32.tf32.tf32.f32 "
        "{%0,%1,%2,%3}, {%4,%5,%6,%7}, {%8,%9}, {%0,%1,%2,%3};"
        : "+f"(c[0]), "+f"(c[1]), "+f"(c[2]), "+f"(c[3])
        : "r"(a[0]), "r"(a[1]), "r"(a[2]), "r"(a[3]), "r"(b[0]), "r"(b[1]));
}
__device__ __forceinline__ uint32_t f2tf32(float x) {
    uint32_t r;
    asm("cvt.rna.tf32.f32 %0, %1;" : "=r"(r) : "f"(x));
    return r;
}

// ===========================================================================
// 3xTF32 mma.sync GEMM: C[M,N] = A[M,K] * W[N,K]^T, fp32-accurate.
// Each operand split into tf32 hi + tf32 lo; D += Ah*Bh + Ah*Bl + Al*Bh.
// BM=128, BN=128, BK=32; 256 threads = 8 warps (4Mx2N); warp tile 32x64.
// ===========================================================================
#define BM 128
#define BN 128
#define BK 32
#define PITCH 36                        // floats per SMEM row (conflict-free)
#define NKT (EMB / BK)                  // 32 k-chunks
#define STAGEF (2 * BM * PITCH)         // floats per stage (A + W tile)
#define GSMEM  (2 * STAGEF * 4)         // bytes, 2 stages = 73728

template <bool SCATTER>
__global__ __launch_bounds__(256) void gemm_mma(
    const float* __restrict__ A,
    const float* __restrict__ W0,
    const float* __restrict__ W1,
    const float* __restrict__ W2,
    float* __restrict__ outp)
{
    const float* Ap;
    const float* Bw;
    float* dst;
    if (SCATTER) {
        Ap  = A;
        Bw  = (blockIdx.z == 0) ? W0 : (blockIdx.z == 1) ? W1 : W2;
        dst = (blockIdx.z == 0) ? g_Q : (blockIdx.z == 1) ? g_K : g_V;
    } else {
        Ap = g_Y; Bw = W0; dst = outp;
    }

    extern __shared__ __align__(16) float sm[];
    const int tid  = threadIdx.x;
    const int wid  = tid >> 5;
    const int lane = tid & 31;
    const int m0   = blockIdx.x * BM;
    const int n0   = blockIdx.y * BN;
    const int wm   = (wid >> 1) * 32;   // warp m offset in tile
    const int wn   = (wid & 1) * 64;    // warp n offset in tile

    const int ldrow = tid >> 3;         // row base for cp.async (…+32*i)
    const int ldc4  = tid & 7;          // float4 column

    const uint32_t sbase = smem_u32(sm);

    // ---- preload chunk 0 ----
    {
        float* As = sm;
        float* Ws = sm + BM * PITCH;
#pragma unroll
        for (int i = 0; i < 4; i++) {
            const int row = ldrow + 32 * i;
            cp_async16(sbase + (uint32_t)((As - sm + row * PITCH + ldc4 * 4) * 4),
                       Ap + (size_t)(m0 + row) * EMB + ldc4 * 4);
            cp_async16(sbase + (uint32_t)((Ws - sm + row * PITCH + ldc4 * 4) * 4),
                       Bw + (size_t)(n0 + row) * EMB + ldc4 * 4);
        }
        cp_commit();
    }

    float acc[2][8][4];
#pragma unroll
    for (int t = 0; t < 2; t++)
#pragma unroll
        for (int u = 0; u < 8; u++)
#pragma unroll
            for (int r = 0; r < 4; r++) acc[t][u][r] = 0.f;

    const int q  = lane & 3;            // k sub-index
    const int g8 = lane >> 2;           // group id 0..7

    for (int kt = 0; kt < NKT; kt++) {
        if (kt + 1 < NKT) {
            float* As = sm + ((kt + 1) & 1) * STAGEF;
            float* Ws = As + BM * PITCH;
            const float* ap = Ap + (size_t)m0 * EMB + (kt + 1) * BK;
            const float* bp = Bw + (size_t)n0 * EMB + (kt + 1) * BK;
#pragma unroll
            for (int i = 0; i < 4; i++) {
                const int row = ldrow + 32 * i;
                cp_async16(sbase + (uint32_t)((As - sm + row * PITCH + ldc4 * 4) * 4),
                           ap + (size_t)row * EMB + ldc4 * 4);
                cp_async16(sbase + (uint32_t)((Ws - sm + row * PITCH + ldc4 * 4) * 4),
                           bp + (size_t)row * EMB + ldc4 * 4);
            }
            cp_commit();
            cp_wait_group<1>();
        } else {
            cp_wait_group<0>();
        }
        __syncthreads();

        const float* As = sm + (kt & 1) * STAGEF;
        const float* Ws = As + BM * PITCH;

#pragma unroll
        for (int ks = 0; ks < 4; ks++) {
            const int k = ks * 8;
            // A fragments: hi/lo split
            uint32_t ah[2][4], al[2][4];
#pragma unroll
            for (int t = 0; t < 2; t++) {
                const int r0 = wm + t * 16 + g8;
                float af[4];
                af[0] = As[r0 * PITCH + k + q];
                af[1] = As[(r0 + 8) * PITCH + k + q];
                af[2] = As[r0 * PITCH + k + q + 4];
                af[3] = As[(r0 + 8) * PITCH + k + q + 4];
#pragma unroll
                for (int r = 0; r < 4; r++) {
                    ah[t][r] = f2tf32(af[r]);
                    al[t][r] = f2tf32(af[r] - __uint_as_float(ah[t][r]));
                }
            }
#pragma unroll
            for (int u = 0; u < 8; u++) {
                const int n = wn + u * 8 + g8;
                float bf0 = Ws[n * PITCH + k + q];
                float bf1 = Ws[n * PITCH + k + q + 4];
                uint32_t bh[2], bl[2];
                bh[0] = f2tf32(bf0);
                bh[1] = f2tf32(bf1);
                bl[0] = f2tf32(bf0 - __uint_as_float(bh[0]));
                bl[1] = f2tf32(bf1 - __uint_as_float(bh[1]));
#pragma unroll
                for (int t = 0; t < 2; t++) {
                    mma_tf32(acc[t][u], ah[t], bh);   // hi*hi
                    mma_tf32(acc[t][u], ah[t], bl);   // hi*lo
                    mma_tf32(acc[t][u], al[t], bh);   // lo*hi
                }
            }
        }
        __syncthreads();
    }

    // ---- epilogue ----
#pragma unroll
    for (int t = 0; t < 2; t++) {
#pragma unroll
        for (int u = 0; u < 8; u++) {
            const int m = m0 + wm + t * 16 + g8;
            const int n = n0 + wn + u * 8 + q * 2;
#pragma unroll
            for (int hh = 0; hh < 2; hh++) {       // row, row+8
                const int mm = m + hh * 8;
                float2 v = make_float2(acc[t][u][hh * 2], acc[t][u][hh * 2 + 1]);
                if (SCATTER) {
                    const int bb = mm >> 11, s = mm & 2047;
                    const int h = n >> 6, d0 = n & 63;
                    *(float2*)(dst + ((((size_t)bb * NH + h) * S_LEN + s) * DH + d0)) = v;
                } else {
                    *(float2*)(dst + (size_t)mm * EMB + n) = v;
                }
            }
        }
    }
}

// ---------------------------------------------------------------------------
// Flash attention, causal (unchanged — known correct).
// ---------------------------------------------------------------------------
#define FLASH_SMEM ((4096 + 64 * 65 + 4096 + 4096) * 4)

__global__ __launch_bounds__(256) void flash_kernel()
{
    const int qi = blockIdx.x;
    const int bh = blockIdx.y;

    extern __shared__ float fsm[];
    float* Qs = fsm;
    float* Ks = Qs + 4096;
    float* Vs = Ks + 64 * 65;
    float* Ps = Vs + 4096;

    const float* Qg  = g_Q + ((size_t)bh * S_LEN + (size_t)qi * 64) * DH;
    const float* Kg0 = g_K + (size_t)bh * S_LEN * DH;
    const float* Vg0 = g_V + (size_t)bh * S_LEN * DH;

    const int tid = threadIdx.x;
    const int tx = tid & 15, ty = tid >> 4;
    const int lr = tid >> 2;
    const int lc = (tid & 3) * 4;

#pragma unroll
    for (int q = 0; q < 4; q++) {
        float4 v = *(const float4*)&Qg[lr * DH + lc + 16 * q];
        float* p = &Qs[lr * 64 + lc + 16 * q];
        p[0] = v.x * 0.125f; p[1] = v.y * 0.125f;
        p[2] = v.z * 0.125f; p[3] = v.w * 0.125f;
    }

    float mprev[4], lsum[4], acc[4][4];
#pragma unroll
    for (int i = 0; i < 4; i++) {
        mprev[i] = -1e30f; lsum[i] = 0.f;
#pragma unroll
        for (int j = 0; j < 4; j++) acc[i][j] = 0.f;
    }

    for (int kj = 0; kj <= qi; kj++) {
        __syncthreads();
        const float* Kg = Kg0 + (size_t)kj * 64 * DH;
        const float* Vg = Vg0 + (size_t)kj * 64 * DH;
#pragma unroll
        for (int q = 0; q < 4; q++) {
            float4 kv = *(const float4*)&Kg[lr * DH + lc + 16 * q];
            float* kp = &Ks[lr * 65 + lc + 16 * q];
            kp[0] = kv.x; kp[1] = kv.y; kp[2] = kv.z; kp[3] = kv.w;
            float4 vv = *(const float4*)&Vg[lr * DH + lc + 16 * q];
            float* vp = &Vs[lr * 64 + lc + 16 * q];
            vp[0] = vv.x; vp[1] = vv.y; vp[2] = vv.z; vp[3] = vv.w;
        }
        __syncthreads();

        float s[4][4] = {};
#pragma unroll 8
        for (int d = 0; d < 64; d++) {
            float qv[4], kv[4];
#pragma unroll
            for (int i = 0; i < 4; i++) qv[i] = Qs[(ty * 4 + i) * 64 + d];
#pragma unroll
            for (int j = 0; j < 4; j++) kv[j] = Ks[(tx * 4 + j) * 65 + d];
#pragma unroll
            for (int i = 0; i < 4; i++)
#pragma unroll
                for (int j = 0; j < 4; j++)
                    s[i][j] = fmaf(qv[i], kv[j], s[i][j]);
        }

        if (kj == qi) {
#pragma unroll
            for (int i = 0; i < 4; i++)
#pragma unroll
                for (int j = 0; j < 4; j++)
                    if (tx * 4 + j > ty * 4 + i) s[i][j] = -1e30f;
        }

#pragma unroll
        for (int i = 0; i < 4; i++) {
            float tm = s[i][0];
#pragma unroll
            for (int j = 1; j < 4; j++) tm = fmaxf(tm, s[i][j]);
#pragma unroll
            for (int o = 1; o < 16; o <<= 1)
                tm = fmaxf(tm, __shfl_xor_sync(0xffffffffu, tm, o));
            const float mnew  = fmaxf(mprev[i], tm);
            const float alpha = __expf(mprev[i] - mnew);
            float psum = 0.f;
#pragma unroll
            for (int j = 0; j < 4; j++) {
                const float p = __expf(s[i][j] - mnew);
                Ps[(ty * 4 + i) * 64 + tx * 4 + j] = p;
                psum += p;
            }
#pragma unroll
            for (int o = 1; o < 16; o <<= 1)
                psum += __shfl_xor_sync(0xffffffffu, psum, o);
            lsum[i]  = lsum[i] * alpha + psum;
            mprev[i] = mnew;
#pragma unroll
            for (int d = 0; d < 4; d++) acc[i][d] *= alpha;
        }
        __syncthreads();

#pragma unroll 8
        for (int j = 0; j < 64; j++) {
            float pv[4], vv[4];
#pragma unroll
            for (int i = 0; i < 4; i++) pv[i] = Ps[(ty * 4 + i) * 64 + j];
#pragma unroll
            for (int d = 0; d < 4; d++) vv[d] = Vs[j * 64 + tx * 4 + d];
#pragma unroll
            for (int i = 0; i < 4; i++)
#pragma unroll
                for (int d = 0; d < 4; d++)
                    acc[i][d] = fmaf(pv[i], vv[d], acc[i][d]);
        }
    }

    const int b = bh >> 4, h = bh & 15;
#pragma unroll
    for (int i = 0; i < 4; i++) {
        const int sq = qi * 64 + ty * 4 + i;
        const float inv = 1.0f / lsum[i];
#pragma unroll
        for (int d = 0; d < 4; d++)
            g_Y[((size_t)(b * S_LEN + sq)) * EMB + h * DH + tx * 4 + d] =
                acc[i][d] * inv;
    }
}

// ---------------------------------------------------------------------------
extern "C" void kernel_launch(void* const* d_in, const int* in_sizes, int n_in,
                              void* d_out, int out_size)
{
    (void)in_sizes; (void)n_in; (void)out_size;
    const float* x  = (const float*)d_in[0];
    const float* Wq = (const float*)d_in[1];
    const float* Wk = (const float*)d_in[2];
    const float* Wv = (const float*)d_in[3];
    const float* Wo = (const float*)d_in[4];
    float* out = (float*)d_out;

    static bool attr_done = false;  // idempotent attribute set (not a work guard)
    if (!attr_done) {
        cudaFuncSetAttribute(gemm_mma<true>,
                             cudaFuncAttributeMaxDynamicSharedMemorySize, GSMEM);
        cudaFuncSetAttribute(gemm_mma<false>,
                             cudaFuncAttributeMaxDynamicSharedMemorySize, GSMEM);
        cudaFuncSetAttribute(flash_kernel,
                             cudaFuncAttributeMaxDynamicSharedMemorySize, FLASH_SMEM);
        attr_done = true;
    }

    // 1) QKV projections on 3xTF32 mma.sync: M=8192, N=1024 per weight
    gemm_mma<true><<<dim3(64, 8, 3), 256, GSMEM>>>(x, Wq, Wk, Wv, nullptr);
    // 2) Causal flash attention (SIMT, unchanged)
    flash_kernel<<<dim3(32, BATCH * NH), 256, FLASH_SMEM>>>();
    // 3) Output projection on 3xTF32 mma.sync
    gemm_mma<false><<<dim3(64, 8), 256, GSMEM>>>(nullptr, Wo, nullptr, nullptr, out);
}

// round 5
// speedup vs baseline: 2.0035x; 1.2984x over previous
#include <cuda_runtime.h>
#include <cstdint>

#define BATCH 4
#define S_LEN 2048
#define EMB   1024
#define NH    16
#define DH    64

// Scratch (allocation-free rule: __device__ globals)
__device__ float g_Q[BATCH * NH * S_LEN * DH];   // [B,H,S,Dh]
__device__ float g_K[BATCH * NH * S_LEN * DH];
__device__ float g_V[BATCH * NH * S_LEN * DH];
__device__ float g_Y[BATCH * S_LEN * EMB];       // merged heads [B,S,E]

// ===========================================================================
// Helpers
// ===========================================================================
__device__ __forceinline__ uint32_t smem_u32(const void* p) {
    uint32_t a;
    asm("{ .reg .u64 t; cvta.to.shared.u64 t, %1; cvt.u32.u64 %0, t; }"
        : "=r"(a) : "l"(p));
    return a;
}
__device__ __forceinline__ void cp_async16(uint32_t s, const void* g) {
    asm volatile("cp.async.cg.shared.global [%0], [%1], 16;" :: "r"(s), "l"(g));
}
__device__ __forceinline__ void cp_commit() {
    asm volatile("cp.async.commit_group;" ::: "memory");
}
template <int N>
__device__ __forceinline__ void cp_wait_group() {
    asm volatile("cp.async.wait_group %0;" :: "n"(N) : "memory");
}
// mma.sync m16n8k8 TF32 (legacy tensor path — compiles for base sm_103)
__device__ __forceinline__ void mma_tf32(float* c, const uint32_t* a, const uint32_t* b) {
    asm volatile(
        "mma.sync.aligned.m16n8k8.row.col.f32.tf32.tf32.f32 "
        "{%0,%1,%2,%3}, {%4,%5,%6,%7}, {%8,%9}, {%0,%1,%2,%3};"
        : "+f"(c[0]), "+f"(c[1]), "+f"(c[2]), "+f"(c[3])
        : "r"(a[0]), "r"(a[1]), "r"(a[2]), "r"(a[3]), "r"(b[0]), "r"(b[1]));
}
__device__ __forceinline__ uint32_t f2tf32(float x) {
    uint32_t r;
    asm("cvt.rna.tf32.f32 %0, %1;" : "=r"(r) : "f"(x));
    return r;
}

// ===========================================================================
// 3xTF32 mma.sync GEMM: C[M,N] = A[M,K] * W[N,K]^T, fp32-accurate.
// (unchanged from round 4 — verified, tensor=61%)
// ===========================================================================
#define BM 128
#define BN 128
#define BK 32
#define PITCH 36
#define NKT (EMB / BK)
#define STAGEF (2 * BM * PITCH)
#define GSMEM  (2 * STAGEF * 4)

template <bool SCATTER>
__global__ __launch_bounds__(256) void gemm_mma(
    const float* __restrict__ A,
    const float* __restrict__ W0,
    const float* __restrict__ W1,
    const float* __restrict__ W2,
    float* __restrict__ outp)
{
    const float* Ap;
    const float* Bw;
    float* dst;
    if (SCATTER) {
        Ap  = A;
        Bw  = (blockIdx.z == 0) ? W0 : (blockIdx.z == 1) ? W1 : W2;
        dst = (blockIdx.z == 0) ? g_Q : (blockIdx.z == 1) ? g_K : g_V;
    } else {
        Ap = g_Y; Bw = W0; dst = outp;
    }

    extern __shared__ __align__(16) float sm[];
    const int tid  = threadIdx.x;
    const int wid  = tid >> 5;
    const int lane = tid & 31;
    const int m0   = blockIdx.x * BM;
    const int n0   = blockIdx.y * BN;
    const int wm   = (wid >> 1) * 32;
    const int wn   = (wid & 1) * 64;

    const int ldrow = tid >> 3;
    const int ldc4  = tid & 7;

    const uint32_t sbase = smem_u32(sm);

    {
        float* As = sm;
        float* Ws = sm + BM * PITCH;
#pragma unroll
        for (int i = 0; i < 4; i++) {
            const int row = ldrow + 32 * i;
            cp_async16(sbase + (uint32_t)((As - sm + row * PITCH + ldc4 * 4) * 4),
                       Ap + (size_t)(m0 + row) * EMB + ldc4 * 4);
            cp_async16(sbase + (uint32_t)((Ws - sm + row * PITCH + ldc4 * 4) * 4),
                       Bw + (size_t)(n0 + row) * EMB + ldc4 * 4);
        }
        cp_commit();
    }

    float acc[2][8][4];
#pragma unroll
    for (int t = 0; t < 2; t++)
#pragma unroll
        for (int u = 0; u < 8; u++)
#pragma unroll
            for (int r = 0; r < 4; r++) acc[t][u][r] = 0.f;

    const int q  = lane & 3;
    const int g8 = lane >> 2;

    for (int kt = 0; kt < NKT; kt++) {
        if (kt + 1 < NKT) {
            float* As = sm + ((kt + 1) & 1) * STAGEF;
            float* Ws = As + BM * PITCH;
            const float* ap = Ap + (size_t)m0 * EMB + (kt + 1) * BK;
            const float* bp = Bw + (size_t)n0 * EMB + (kt + 1) * BK;
#pragma unroll
            for (int i = 0; i < 4; i++) {
                const int row = ldrow + 32 * i;
                cp_async16(sbase + (uint32_t)((As - sm + row * PITCH + ldc4 * 4) * 4),
                           ap + (size_t)row * EMB + ldc4 * 4);
                cp_async16(sbase + (uint32_t)((Ws - sm + row * PITCH + ldc4 * 4) * 4),
                           bp + (size_t)row * EMB + ldc4 * 4);
            }
            cp_commit();
            cp_wait_group<1>();
        } else {
            cp_wait_group<0>();
        }
        __syncthreads();

        const float* As = sm + (kt & 1) * STAGEF;
        const float* Ws = As + BM * PITCH;

#pragma unroll
        for (int ks = 0; ks < 4; ks++) {
            const int k = ks * 8;
            uint32_t ah[2][4], al[2][4];
#pragma unroll
            for (int t = 0; t < 2; t++) {
                const int r0 = wm + t * 16 + g8;
                float af[4];
                af[0] = As[r0 * PITCH + k + q];
                af[1] = As[(r0 + 8) * PITCH + k + q];
                af[2] = As[r0 * PITCH + k + q + 4];
                af[3] = As[(r0 + 8) * PITCH + k + q + 4];
#pragma unroll
                for (int r = 0; r < 4; r++) {
                    ah[t][r] = f2tf32(af[r]);
                    al[t][r] = f2tf32(af[r] - __uint_as_float(ah[t][r]));
                }
            }
#pragma unroll
            for (int u = 0; u < 8; u++) {
                const int n = wn + u * 8 + g8;
                float bf0 = Ws[n * PITCH + k + q];
                float bf1 = Ws[n * PITCH + k + q + 4];
                uint32_t bh[2], bl[2];
                bh[0] = f2tf32(bf0);
                bh[1] = f2tf32(bf1);
                bl[0] = f2tf32(bf0 - __uint_as_float(bh[0]));
                bl[1] = f2tf32(bf1 - __uint_as_float(bh[1]));
#pragma unroll
                for (int t = 0; t < 2; t++) {
                    mma_tf32(acc[t][u], ah[t], bh);
                    mma_tf32(acc[t][u], ah[t], bl);
                    mma_tf32(acc[t][u], al[t], bh);
                }
            }
        }
        __syncthreads();
    }

#pragma unroll
    for (int t = 0; t < 2; t++) {
#pragma unroll
        for (int u = 0; u < 8; u++) {
            const int m = m0 + wm + t * 16 + g8;
            const int n = n0 + wn + u * 8 + q * 2;
#pragma unroll
            for (int hh = 0; hh < 2; hh++) {
                const int mm = m + hh * 8;
                float2 v = make_float2(acc[t][u][hh * 2], acc[t][u][hh * 2 + 1]);
                if (SCATTER) {
                    const int bb = mm >> 11, s = mm & 2047;
                    const int h = n >> 6, d0 = n & 63;
                    *(float2*)(dst + ((((size_t)bb * NH + h) * S_LEN + s) * DH + d0)) = v;
                } else {
                    *(float2*)(dst + (size_t)mm * EMB + n) = v;
                }
            }
        }
    }
}

// ===========================================================================
// mma.sync flash attention, causal. Block = 128 q-rows; k-tiles of 64.
// 8 warps, each owns a 16-row strip. QK^T in 3xTF32, PV in 1xTF32.
// Q fragments register-resident; Q smem reused as P buffer.
// ===========================================================================
#define QPIT 68
#define KPIT 68
#define VPIT 72
#define QP_F   (128 * QPIT)                 // 8704 floats (Q then P)
#define KST_F  (64 * KPIT)                  // 4352 per stage
#define VST_F  (64 * VPIT)                  // 4608 per stage
#define FLASH_SMEM ((QP_F + 2 * KST_F + 2 * VST_F) * 4)   // 106496 B

__global__ __launch_bounds__(256) void flash_mma()
{
    const int qi = blockIdx.x;              // q-tile: rows qi*128..+127
    const int bh = blockIdx.y;              // b*NH+h

    extern __shared__ __align__(16) float sm[];
    float* QP = sm;
    float* Kb = sm + QP_F;
    float* Vb = Kb + 2 * KST_F;

    const int tid  = threadIdx.x;
    const int wid  = tid >> 5;
    const int lane = tid & 31;
    const int g8   = lane >> 2;
    const int q    = lane & 3;
    const int wm   = wid * 16;              // warp row strip

    const float* Qg = g_Q + ((size_t)bh * S_LEN + (size_t)qi * 128) * DH;
    const float* Kg = g_K + (size_t)bh * S_LEN * DH;
    const float* Vg = g_V + (size_t)bh * S_LEN * DH;

    const uint32_t sbase = smem_u32(sm);
    const uint32_t kboff = (uint32_t)(QP_F * 4);
    const uint32_t vboff = (uint32_t)((QP_F + 2 * KST_F) * 4);

    // ---- Q tile via cp.async (group 0) ----
#pragma unroll
    for (int j = 0; j < 8; j++) {
        const int f = tid + 256 * j, row = f >> 4, c4 = f & 15;
        cp_async16(sbase + (uint32_t)((row * QPIT + c4 * 4) * 4),
                   Qg + row * DH + c4 * 4);
    }
    cp_commit();
    // ---- K/V tile 0 into stage 0 (group 1) ----
#pragma unroll
    for (int j = 0; j < 4; j++) {
        const int f = tid + 256 * j, row = f >> 4, c4 = f & 15;
        cp_async16(sbase + kboff + (uint32_t)((row * KPIT + c4 * 4) * 4),
                   Kg + row * DH + c4 * 4);
        cp_async16(sbase + vboff + (uint32_t)((row * VPIT + c4 * 4) * 4),
                   Vg + row * DH + c4 * 4);
    }
    cp_commit();

    cp_wait_group<1>();                     // Q resident
    __syncthreads();

    // ---- hoist Q fragments (3x split); then QP becomes the P buffer ----
    uint32_t qh[8][4], ql[8][4];
#pragma unroll
    for (int kc = 0; kc < 8; kc++) {
        float f0 = QP[(wm + g8) * QPIT + kc * 8 + q];
        float f1 = QP[(wm + g8 + 8) * QPIT + kc * 8 + q];
        float f2 = QP[(wm + g8) * QPIT + kc * 8 + q + 4];
        float f3 = QP[(wm + g8 + 8) * QPIT + kc * 8 + q + 4];
        qh[kc][0] = f2tf32(f0); ql[kc][0] = f2tf32(f0 - __uint_as_float(qh[kc][0]));
        qh[kc][1] = f2tf32(f1); ql[kc][1] = f2tf32(f1 - __uint_as_float(qh[kc][1]));
        qh[kc][2] = f2tf32(f2); ql[kc][2] = f2tf32(f2 - __uint_as_float(qh[kc][2]));
        qh[kc][3] = f2tf32(f3); ql[kc][3] = f2tf32(f3 - __uint_as_float(qh[kc][3]));
    }
    __syncthreads();                        // Q reads done before P stores

    float m0 = -1e30f, m1 = -1e30f, l0 = 0.f, l1 = 0.f;
    float o[8][4];
#pragma unroll
    for (int u = 0; u < 8; u++)
#pragma unroll
        for (int r = 0; r < 4; r++) o[u][r] = 0.f;

    const int row0 = qi * 128 + wm + g8;
    const int row1 = row0 + 8;
    const int last = 2 * qi + 1;

    for (int kt = 0; kt <= last; kt++) {
        if (kt < last) {
            const int st = (kt + 1) & 1;
            const float* kp = Kg + (size_t)(kt + 1) * 64 * DH;
            const float* vp = Vg + (size_t)(kt + 1) * 64 * DH;
#pragma unroll
            for (int j = 0; j < 4; j++) {
                const int f = tid + 256 * j, row = f >> 4, c4 = f & 15;
                cp_async16(sbase + kboff + (uint32_t)((st * KST_F + row * KPIT + c4 * 4) * 4),
                           kp + row * DH + c4 * 4);
                cp_async16(sbase + vboff + (uint32_t)((st * VST_F + row * VPIT + c4 * 4) * 4),
                           vp + row * DH + c4 * 4);
            }
            cp_commit();
            cp_wait_group<1>();
        } else {
            cp_wait_group<0>();
        }
        __syncthreads();

        const float* Kst = Kb + (kt & 1) * KST_F;
        const float* Vst = Vb + (kt & 1) * VST_F;

        // ---- S = (Q K^T) 3xTF32 ----
        float s[8][4];
#pragma unroll
        for (int u = 0; u < 8; u++)
#pragma unroll
            for (int r = 0; r < 4; r++) s[u][r] = 0.f;

#pragma unroll
        for (int kc = 0; kc < 8; kc++) {
#pragma unroll
            for (int u = 0; u < 8; u++) {
                float bf0 = Kst[(u * 8 + g8) * KPIT + kc * 8 + q];
                float bf1 = Kst[(u * 8 + g8) * KPIT + kc * 8 + q + 4];
                uint32_t bh[2], bl[2];
                bh[0] = f2tf32(bf0);
                bh[1] = f2tf32(bf1);
                bl[0] = f2tf32(bf0 - __uint_as_float(bh[0]));
                bl[1] = f2tf32(bf1 - __uint_as_float(bh[1]));
                mma_tf32(s[u], qh[kc], bh);
                mma_tf32(s[u], qh[kc], bl);
                mma_tf32(s[u], ql[kc], bh);
            }
        }

        // scale
#pragma unroll
        for (int u = 0; u < 8; u++)
#pragma unroll
            for (int r = 0; r < 4; r++) s[u][r] *= 0.125f;

        // causal mask (only tiles touching the diagonal)
        if (kt >= 2 * qi) {
            const int cb = kt * 64;
#pragma unroll
            for (int u = 0; u < 8; u++) {
                const int c = cb + u * 8 + 2 * q;
                if (c     > row0) s[u][0] = -1e30f;
                if (c + 1 > row0) s[u][1] = -1e30f;
                if (c     > row1) s[u][2] = -1e30f;
                if (c + 1 > row1) s[u][3] = -1e30f;
            }
        }

        // ---- online softmax (rows row0, row1; quad reduction) ----
        float tm0 = -1e30f, tm1 = -1e30f;
#pragma unroll
        for (int u = 0; u < 8; u++) {
            tm0 = fmaxf(tm0, fmaxf(s[u][0], s[u][1]));
            tm1 = fmaxf(tm1, fmaxf(s[u][2], s[u][3]));
        }
        tm0 = fmaxf(tm0, __shfl_xor_sync(0xffffffffu, tm0, 1));
        tm0 = fmaxf(tm0, __shfl_xor_sync(0xffffffffu, tm0, 2));
        tm1 = fmaxf(tm1, __shfl_xor_sync(0xffffffffu, tm1, 1));
        tm1 = fmaxf(tm1, __shfl_xor_sync(0xffffffffu, tm1, 2));

        const float mn0 = fmaxf(m0, tm0);
        const float mn1 = fmaxf(m1, tm1);
        const float a0 = __expf(m0 - mn0);
        const float a1 = __expf(m1 - mn1);

        float ps0 = 0.f, ps1 = 0.f;
#pragma unroll
        for (int u = 0; u < 8; u++) {
            const float p00 = __expf(s[u][0] - mn0);
            const float p01 = __expf(s[u][1] - mn0);
            const float p10 = __expf(s[u][2] - mn1);
            const float p11 = __expf(s[u][3] - mn1);
            ps0 += p00 + p01;
            ps1 += p10 + p11;
            *(float2*)&QP[(wm + g8) * QPIT + u * 8 + 2 * q]     = make_float2(p00, p01);
            *(float2*)&QP[(wm + g8 + 8) * QPIT + u * 8 + 2 * q] = make_float2(p10, p11);
        }
        ps0 += __shfl_xor_sync(0xffffffffu, ps0, 1);
        ps0 += __shfl_xor_sync(0xffffffffu, ps0, 2);
        ps1 += __shfl_xor_sync(0xffffffffu, ps1, 1);
        ps1 += __shfl_xor_sync(0xffffffffu, ps1, 2);

        l0 = l0 * a0 + ps0;
        l1 = l1 * a1 + ps1;
        m0 = mn0;
        m1 = mn1;
#pragma unroll
        for (int u = 0; u < 8; u++) {
            o[u][0] *= a0; o[u][1] *= a0;
            o[u][2] *= a1; o[u][3] *= a1;
        }
        __syncwarp();   // P visible within warp (A-frags read cross-lane)

        // ---- O += P @ V (1xTF32) ----
#pragma unroll
        for (int kc = 0; kc < 8; kc++) {
            uint32_t a[4];
            a[0] = f2tf32(QP[(wm + g8) * QPIT + kc * 8 + q]);
            a[1] = f2tf32(QP[(wm + g8 + 8) * QPIT + kc * 8 + q]);
            a[2] = f2tf32(QP[(wm + g8) * QPIT + kc * 8 + q + 4]);
            a[3] = f2tf32(QP[(wm + g8 + 8) * QPIT + kc * 8 + q + 4]);
#pragma unroll
            for (int u = 0; u < 8; u++) {
                uint32_t b[2];
                b[0] = f2tf32(Vst[(kc * 8 + q) * VPIT + u * 8 + g8]);
                b[1] = f2tf32(Vst[(kc * 8 + q + 4) * VPIT + u * 8 + g8]);
                mma_tf32(o[u], a, b);
            }
        }
        // next tile's P stores are after the loop-head __syncthreads
    }

    // ---- epilogue: normalize, write merged-head [B,S,E] ----
    const int b = bh >> 4, h = bh & 15;
    const float i0 = 1.0f / l0;
    const float i1 = 1.0f / l1;
    float* Y0 = g_Y + ((size_t)b * S_LEN + row0) * EMB + h * DH;
    float* Y1 = g_Y + ((size_t)b * S_LEN + row1) * EMB + h * DH;
#pragma unroll
    for (int u = 0; u < 8; u++) {
        const int c = u * 8 + 2 * q;
        *(float2*)&Y0[c] = make_float2(o[u][0] * i0, o[u][1] * i0);
        *(float2*)&Y1[c] = make_float2(o[u][2] * i1, o[u][3] * i1);
    }
}

// ---------------------------------------------------------------------------
extern "C" void kernel_launch(void* const* d_in, const int* in_sizes, int n_in,
                              void* d_out, int out_size)
{
    (void)in_sizes; (void)n_in; (void)out_size;
    const float* x  = (const float*)d_in[0];
    const float* Wq = (const float*)d_in[1];
    const float* Wk = (const float*)d_in[2];
    const float* Wv = (const float*)d_in[3];
    const float* Wo = (const float*)d_in[4];
    float* out = (float*)d_out;

    static bool attr_done = false;  // idempotent attribute set (not a work guard)
    if (!attr_done) {
        cudaFuncSetAttribute(gemm_mma<true>,
                             cudaFuncAttributeMaxDynamicSharedMemorySize, GSMEM);
        cudaFuncSetAttribute(gemm_mma<false>,
                             cudaFuncAttributeMaxDynamicSharedMemorySize, GSMEM);
        cudaFuncSetAttribute(flash_mma,
                             cudaFuncAttributeMaxDynamicSharedMemorySize, FLASH_SMEM);
        attr_done = true;
    }

    // 1) QKV projections on 3xTF32 mma.sync
    gemm_mma<true><<<dim3(64, 8, 3), 256, GSMEM>>>(x, Wq, Wk, Wv, nullptr);
    // 2) Causal flash attention on mma.sync (3xTF32 QK^T, 1xTF32 PV)
    flash_mma<<<dim3(16, BATCH * NH), 256, FLASH_SMEM>>>();
    // 3) Output projection on 3xTF32 mma.sync
    gemm_mma<false><<<dim3(64, 8), 256, GSMEM>>>(nullptr, Wo, nullptr, nullptr, out);
}